// round 2
// baseline (speedup 1.0000x reference)
#include <cuda_runtime.h>
#include <stdint.h>

// PointPillars BEV scatter: (M,3) coords + (M,64) features -> (B,64,496,432)
#define BEV_H 496
#define BEV_W 432
#define NB    4
#define NC    64
#define W4    (BEV_W / 4)                 // 108 float4-cells per row
#define NCELL (NB * BEV_H * W4)           // 214272 total float4-cells

// Inverse map: BEV cell -> pillar index + 1 (0 = empty). 3.43 MB device global.
// SELF-CLEANING: zero-initialized at module load; the gather kernel writes
// zeros back to every occupied int4 it reads, so the map is all-zero again at
// the end of every kernel_launch call. No explicit clear kernel needed.
__device__ int g_map[NB * BEV_H * BEV_W];

// ---------------------------------------------------------------------------
// Kernel 1: scatter pillar index+1 into the map (coords are collision-free).
__global__ void scatter_idx_kernel(const int* __restrict__ coords, int M) {
    int m = blockIdx.x * blockDim.x + threadIdx.x;
    if (m < M) {
        int b = coords[3 * m + 0];
        int y = coords[3 * m + 1];
        int x = coords[3 * m + 2];
        g_map[(b * BEV_H + y) * BEV_W + x] = m + 1;
    }
}

// ---------------------------------------------------------------------------
// Kernel 2: dense coalesced gather + map self-clean.
// Grid-stride over all 214272 float4-cells; each thread owns one cell's full
// 64 channels, emitting one float4 store per channel (rows are 1728 B, so
// all int4/float4 accesses are 16B-aligned).
__global__ __launch_bounds__(256) void gather_kernel(
    const float* __restrict__ feat, float* __restrict__ out) {
    const int stride = gridDim.x * blockDim.x;
    for (int i = blockIdx.x * blockDim.x + threadIdx.x; i < NCELL; i += stride) {
        int b   = i / (BEV_H * W4);
        int rem = i - b * (BEV_H * W4);
        int y   = rem / W4;
        int x4  = (rem - y * W4) * 4;

        int4* mpp = reinterpret_cast<int4*>(&g_map[(b * BEV_H + y) * BEV_W + x4]);
        const int4 mp = *mpp;
        if (mp.x | mp.y | mp.z | mp.w) {
            *mpp = make_int4(0, 0, 0, 0);   // self-clean for the next call
        }

        const float* f0 = mp.x ? feat + (size_t)(mp.x - 1) * NC : nullptr;
        const float* f1 = mp.y ? feat + (size_t)(mp.y - 1) * NC : nullptr;
        const float* f2 = mp.z ? feat + (size_t)(mp.z - 1) * NC : nullptr;
        const float* f3 = mp.w ? feat + (size_t)(mp.w - 1) * NC : nullptr;

        float* outp = out + ((size_t)(b * NC) * BEV_H + y) * BEV_W + x4;
        const size_t cstride = (size_t)BEV_H * BEV_W;

#pragma unroll 16
        for (int c = 0; c < NC; ++c) {
            float4 v;
            v.x = f0 ? __ldg(f0 + c) : 0.0f;
            v.y = f1 ? __ldg(f1 + c) : 0.0f;
            v.z = f2 ? __ldg(f2 + c) : 0.0f;
            v.w = f3 ? __ldg(f3 + c) : 0.0f;
            *reinterpret_cast<float4*>(outp) = v;
            outp += cstride;
        }
    }
}

// ---------------------------------------------------------------------------
extern "C" void kernel_launch(void* const* d_in, const int* in_sizes, int n_in,
                              void* d_out, int out_size) {
    const int*   coords = (const int*)d_in[0];    // (M, 3) int32
    const float* feat   = (const float*)d_in[1];  // (M, 64) float32
    float*       out    = (float*)d_out;          // (4, 64, 496, 432) float32
    const int M = in_sizes[0] / 3;

    // 1) scatter pillar indices into the (already-zero) map
    scatter_idx_kernel<<<(M + 255) / 256, 256>>>(coords, M);

    // 2) dense gather into output; clears the map as it goes.
    //    592 blocks = 4 per SM (148 SMs), grid-stride over 214272 cells.
    gather_kernel<<<592, 256>>>(feat, out);
}

// round 3
// speedup vs baseline: 2.0267x; 2.0267x over previous
#include <cuda_runtime.h>
#include <stdint.h>

// PointPillars BEV scatter: (M,3) coords + (M,64) features -> (B,64,496,432)
#define BEV_H 496
#define BEV_W 432
#define NB    4
#define NC    64
#define W4    (BEV_W / 4)                 // 108 float4-cells per row
#define NCELL (NB * BEV_H * W4)           // 214272 total float4-cells
#define CPT   16                          // channels per thread
#define NCG   (NC / CPT)                  // 4 channel-groups
#define CPB   64                          // cells per block (block = 64*4 = 256 thr)

// Inverse map: BEV cell -> pillar index + 1 (0 = empty). 3.43 MB device global.
// SELF-CLEANING: zero at module load; gather reads it, syncs, then cg0 writes
// zeros back to occupied entries -> all-zero again at end of every call.
__device__ int g_map[NB * BEV_H * BEV_W];

// ---------------------------------------------------------------------------
// Kernel 1: scatter pillar index+1 into the map (coords are collision-free).
__global__ void scatter_idx_kernel(const int* __restrict__ coords, int M) {
    int m = blockIdx.x * blockDim.x + threadIdx.x;
    if (m < M) {
        int b = coords[3 * m + 0];
        int y = coords[3 * m + 1];
        int x = coords[3 * m + 2];
        g_map[(b * BEV_H + y) * BEV_W + x] = m + 1;
    }
}

// ---------------------------------------------------------------------------
// Kernel 2: dense gather, channel-split 4 ways.
// t%64 -> cell within block's 64-cell span, t/64 -> channel group (16 ch).
// Per thread: 1 int4 map load, <=16 float4 feature loads, 16 float4 stores.
// Grid = NCELL/CPB = 3348 blocks exactly; every lane has real work.
__global__ __launch_bounds__(256) void gather_kernel(
    const float* __restrict__ feat, float* __restrict__ out) {
    const int t         = threadIdx.x;
    const int cellLocal = t & (CPB - 1);
    const int cg        = t >> 6;                     // 0..3
    const int cell      = blockIdx.x * CPB + cellLocal;

    const int b   = cell / (BEV_H * W4);
    const int rem = cell - b * (BEV_H * W4);
    const int y   = rem / W4;
    const int x4  = (rem - y * W4) * 4;

    int4* mpp = reinterpret_cast<int4*>(&g_map[(b * BEV_H + y) * BEV_W + x4]);
    const int4 mp = *mpp;
    __syncthreads();                                  // all 4 cgroups have read
    if (cg == 0 && (mp.x | mp.y | mp.z | mp.w)) {
        *mpp = make_int4(0, 0, 0, 0);                 // self-clean for next call
    }

    const int pi[4] = { mp.x, mp.y, mp.z, mp.w };
    float4 v[4][4];                                   // [pillar][quad of 4 ch]
#pragma unroll
    for (int p = 0; p < 4; ++p) {
        if (pi[p]) {
            const float4* fp = reinterpret_cast<const float4*>(
                feat + (size_t)(pi[p] - 1) * NC + cg * CPT);
            v[p][0] = fp[0]; v[p][1] = fp[1]; v[p][2] = fp[2]; v[p][3] = fp[3];
        } else {
            v[p][0] = v[p][1] = v[p][2] = v[p][3] = make_float4(0.f, 0.f, 0.f, 0.f);
        }
    }

    float* outp = out + ((size_t)(b * NC + cg * CPT) * BEV_H + y) * BEV_W + x4;
    const size_t cs = (size_t)BEV_H * BEV_W;
#pragma unroll
    for (int q = 0; q < 4; ++q) {
        *reinterpret_cast<float4*>(outp) =
            make_float4(v[0][q].x, v[1][q].x, v[2][q].x, v[3][q].x);
        outp += cs;
        *reinterpret_cast<float4*>(outp) =
            make_float4(v[0][q].y, v[1][q].y, v[2][q].y, v[3][q].y);
        outp += cs;
        *reinterpret_cast<float4*>(outp) =
            make_float4(v[0][q].z, v[1][q].z, v[2][q].z, v[3][q].z);
        outp += cs;
        *reinterpret_cast<float4*>(outp) =
            make_float4(v[0][q].w, v[1][q].w, v[2][q].w, v[3][q].w);
        outp += cs;
    }
}

// ---------------------------------------------------------------------------
extern "C" void kernel_launch(void* const* d_in, const int* in_sizes, int n_in,
                              void* d_out, int out_size) {
    const int*   coords = (const int*)d_in[0];    // (M, 3) int32
    const float* feat   = (const float*)d_in[1];  // (M, 64) float32
    float*       out    = (float*)d_out;          // (4, 64, 496, 432) float32
    const int M = in_sizes[0] / 3;

    scatter_idx_kernel<<<(M + 255) / 256, 256>>>(coords, M);
    gather_kernel<<<NCELL / CPB, 256>>>(feat, out);
}